// round 3
// baseline (speedup 1.0000x reference)
#include <cuda_runtime.h>

#define G       37
#define NPATCH  (G * G)          // 1369
#define D       768
#define NCUE    5
#define STOK    (NCUE + NPATCH)  // 1374
#define BATCH   128
#define EPSN    1e-12f

#define BLOCKS_PER_BATCH 11
#define PPB              125     // ceil(1369/11)

// packed argmax scratch: high 32 = orderable sim key, low 32 = ~idx (lowest idx wins ties)
__device__ unsigned long long g_best[BATCH * NCUE];

__device__ __forceinline__ unsigned f2key(float f) {
    unsigned u = __float_as_uint(f);
    return (u & 0x80000000u) ? ~u : (u | 0x80000000u);
}

__global__ void init_best_kernel() {
    int i = blockIdx.x * blockDim.x + threadIdx.x;
    if (i < BATCH * NCUE) g_best[i] = 0ull;
}

// ---------------------------------------------------------------------------
// Kernel 1: per-(batch, cue) argmax over 1369 patch dot-products.
// One warp handles 4 patches per iteration so each cue float4 loaded from
// smem is reused 4x (LDS crossbar stays under the HBM-bound cycle budget).
// ---------------------------------------------------------------------------
__global__ __launch_bounds__(256) void argmax_kernel(const float* __restrict__ tokens) {
    __shared__ float cue_sm[NCUE * D];   // 15360 B

    const int b = blockIdx.y;
    const float* base = tokens + (size_t)b * STOK * D;

    // cues = tokens[b, 0:5, :], contiguous
    for (int i = threadIdx.x; i < NCUE * D; i += 256)
        cue_sm[i] = base[i];
    __syncthreads();

    const int lane = threadIdx.x & 31;
    const int warp = threadIdx.x >> 5;
    const int p0   = blockIdx.x * PPB;
    const int pend = min(p0 + PPB, NPATCH);

    const float4* cue4    = (const float4*)cue_sm;
    const float*  patches = base + NCUE * D;

    unsigned long long best[NCUE];
#pragma unroll
    for (int c = 0; c < NCUE; c++) best[c] = 0ull;

    for (int g = p0 + warp * 4; g < pend; g += 32) {
        // 4 patches; tail clamps to last patch (duplicate (sim,idx) is idempotent under max)
        int pidx[4];
        const float4* pp[4];
#pragma unroll
        for (int p = 0; p < 4; p++) {
            pidx[p] = min(g + p, NPATCH - 1);
            pp[p]   = (const float4*)(patches + (size_t)pidx[p] * D);
        }

        float acc[NCUE][4];
#pragma unroll
        for (int c = 0; c < NCUE; c++)
#pragma unroll
            for (int p = 0; p < 4; p++) acc[c][p] = 0.0f;

#pragma unroll
        for (int i = 0; i < 6; i++) {           // 6 x 128 dims
            const int fi = lane + 32 * i;       // float4 index within row (0..191)
            float4 pv[4];
#pragma unroll
            for (int p = 0; p < 4; p++) pv[p] = pp[p][fi];
#pragma unroll
            for (int c = 0; c < NCUE; c++) {
                const float4 cv = cue4[c * (D / 4) + fi];
#pragma unroll
                for (int p = 0; p < 4; p++) {
                    acc[c][p] = fmaf(cv.x, pv[p].x, acc[c][p]);
                    acc[c][p] = fmaf(cv.y, pv[p].y, acc[c][p]);
                    acc[c][p] = fmaf(cv.z, pv[p].z, acc[c][p]);
                    acc[c][p] = fmaf(cv.w, pv[p].w, acc[c][p]);
                }
            }
        }

        // warp butterfly reduce each of the 20 sums
#pragma unroll
        for (int c = 0; c < NCUE; c++)
#pragma unroll
            for (int p = 0; p < 4; p++) {
                float s = acc[c][p];
                s += __shfl_xor_sync(0xffffffffu, s, 16);
                s += __shfl_xor_sync(0xffffffffu, s, 8);
                s += __shfl_xor_sync(0xffffffffu, s, 4);
                s += __shfl_xor_sync(0xffffffffu, s, 2);
                s += __shfl_xor_sync(0xffffffffu, s, 1);
                acc[c][p] = s;
            }

#pragma unroll
        for (int p = 0; p < 4; p++) {
            const unsigned lowbits = 0xFFFFFFFFu - (unsigned)pidx[p];
#pragma unroll
            for (int c = 0; c < NCUE; c++) {
                unsigned long long k =
                    ((unsigned long long)f2key(acc[c][p]) << 32) | lowbits;
                best[c] = (k > best[c]) ? k : best[c];
            }
        }
    }

    if (lane == 0) {
#pragma unroll
        for (int c = 0; c < NCUE; c++)
            atomicMax(&g_best[b * NCUE + c], best[c]);
    }
}

// ---------------------------------------------------------------------------
// Kernel 2: build + normalize 10 output tokens per batch.
// blockIdx.x = token t (0..9), blockIdx.y = batch. 256 threads, 3 dims/thread.
// ---------------------------------------------------------------------------
__global__ __launch_bounds__(256) void gather_kernel(const float* __restrict__ tokens,
                                                     float* __restrict__ out) {
    const int t = blockIdx.x;
    const int b = blockIdx.y;
    const float* base = tokens + (size_t)b * STOK * D;
    const int tid = threadIdx.x;

    float v[3];

    if (t < NCUE) {
        const float* row = base + (size_t)t * D;
#pragma unroll
        for (int j = 0; j < 3; j++) v[j] = row[tid + 256 * j];
    } else {
        const int c = t - NCUE;
        const unsigned long long key = g_best[b * NCUE + c];
        const int idx = (int)(0xFFFFFFFFu - (unsigned)(key & 0xFFFFFFFFu));
        const int h = idx / G, w = idx % G;
        const int r0 = max(h - 1, 0), r1 = min(h + 1, G - 1);
        const int c0 = max(w - 1, 0), c1 = min(w + 1, G - 1);
        const float inv = 1.0f / (float)((r1 - r0 + 1) * (c1 - c0 + 1));
#pragma unroll
        for (int j = 0; j < 3; j++) v[j] = 0.0f;
        for (int r = r0; r <= r1; r++)
            for (int cc = c0; cc <= c1; cc++) {
                const float* prow = base + (size_t)(NCUE + r * G + cc) * D;
#pragma unroll
                for (int j = 0; j < 3; j++) v[j] += prow[tid + 256 * j];
            }
#pragma unroll
        for (int j = 0; j < 3; j++) v[j] *= inv;
    }

    // block reduce sum of squares
    float ss = v[0] * v[0] + v[1] * v[1] + v[2] * v[2];
#pragma unroll
    for (int o = 16; o > 0; o >>= 1) ss += __shfl_xor_sync(0xffffffffu, ss, o);

    __shared__ float red[8];
    const int lane = tid & 31, warp = tid >> 5;
    if (lane == 0) red[warp] = ss;
    __syncthreads();
    if (warp == 0) {
        float s2 = (lane < 8) ? red[lane] : 0.0f;
        s2 += __shfl_xor_sync(0xffffffffu, s2, 4);
        s2 += __shfl_xor_sync(0xffffffffu, s2, 2);
        s2 += __shfl_xor_sync(0xffffffffu, s2, 1);
        if (lane == 0) red[0] = s2;
    }
    __syncthreads();

    const float norm  = sqrtf(red[0]);
    const float scale = 1.0f / fmaxf(norm, EPSN);

    float* orow = out + ((size_t)b * 10 + t) * D;
#pragma unroll
    for (int j = 0; j < 3; j++) orow[tid + 256 * j] = v[j] * scale;
}

extern "C" void kernel_launch(void* const* d_in, const int* in_sizes, int n_in,
                              void* d_out, int out_size) {
    const float* tokens = (const float*)d_in[0];
    float* out = (float*)d_out;

    init_best_kernel<<<3, 256>>>();
    argmax_kernel<<<dim3(BLOCKS_PER_BATCH, BATCH), 256>>>(tokens);
    gather_kernel<<<dim3(10, BATCH), 256>>>(tokens, out);
}

// round 4
// speedup vs baseline: 1.9597x; 1.9597x over previous
#include <cuda_runtime.h>

#define G       37
#define NPATCH  (G * G)          // 1369
#define D       768
#define NCUE    5
#define STOK    (NCUE + NPATCH)  // 1374
#define BATCH   128
#define EPSN    1e-12f

#define TPB     128              // threads per argmax block (1 patch per thread)
#define PTILE   128              // patches per tile
#define NTILE   11               // ceil(1369/128)
#define DC      32               // dims per pipeline stage
#define NS      (D / DC)         // 24 stages
#define F4ROW   (DC / 4)         // 8 float4 per row per stage
#define STAGE_F4 (PTILE * F4ROW) // 1024 float4 = 16KB per buffer

// packed argmax scratch: high 32 = orderable sim key, low 32 = ~idx (lowest idx wins ties)
// zero-initialized at module load; gather_kernel resets it to 0 every call.
__device__ unsigned long long g_best[BATCH * NCUE];

__device__ __forceinline__ unsigned f2key(float f) {
    unsigned u = __float_as_uint(f);
    return (u & 0x80000000u) ? ~u : (u | 0x80000000u);
}
// Blackwell packed f32x2 FMA (2 fp32 FMAs per instruction)
__device__ __forceinline__ void fma2(unsigned long long& d, unsigned long long a,
                                     unsigned long long b) {
    asm volatile("fma.rn.f32x2 %0, %1, %2, %0;" : "+l"(d) : "l"(a), "l"(b));
}
__device__ __forceinline__ void lds_v2u64(unsigned long long& lo, unsigned long long& hi,
                                          unsigned addr) {
    asm volatile("ld.shared.v2.u64 {%0, %1}, [%2];" : "=l"(lo), "=l"(hi) : "r"(addr));
}
__device__ __forceinline__ void cp16(unsigned dst, const void* src) {
    asm volatile("cp.async.cg.shared.global [%0], [%1], 16;" :: "r"(dst), "l"(src)
                 : "memory");
}

// ---------------------------------------------------------------------------
// Kernel 1: per-(batch,cue) argmax over patch dot-products.
// cp.async double-buffered smem pipeline; each thread owns one patch row and
// accumulates its 5 cue dot products with packed f32x2 FMAs. No cross-lane
// reduction in the hot loop.
// ---------------------------------------------------------------------------
__global__ __launch_bounds__(TPB) void argmax_kernel(const float* __restrict__ tokens) {
    __shared__ float4 stage_buf[2][STAGE_F4];          // 32 KB
    __shared__ float  cue_sm[NCUE * D];                // 15 KB
    __shared__ unsigned long long warp_best[TPB / 32][NCUE];

    const int b = blockIdx.y;
    const int t = threadIdx.x;
    const float* base = tokens + (size_t)b * STOK * D;

    // cues = tokens[b, 0:5, :] (contiguous, float4)
    {
        const float4* cg = (const float4*)base;
        float4* cs = (float4*)cue_sm;
        for (int i = t; i < NCUE * D / 4; i += TPB) cs[i] = cg[i];
    }

    const int p0 = blockIdx.x * PTILE;
    const float4* patch4 = (const float4*)(base + NCUE * D);   // 192 float4 / row

    // Per-thread staging descriptors: 8 passes of (16 rows x 8 segs).
    const int s4 = t & 7;
    const float4* gsrc[8];
    unsigned sdst[8];
    const unsigned sb0 = (unsigned)__cvta_generic_to_shared(&stage_buf[0][0]);
#pragma unroll
    for (int pass = 0; pass < 8; pass++) {
        int r    = pass * 16 + (t >> 3);
        int pidx = min(p0 + r, NPATCH - 1);   // tail clamps (idempotent under max)
        gsrc[pass] = patch4 + (size_t)pidx * (D / 4) + s4;
        sdst[pass] = sb0 + (unsigned)((r * F4ROW + (s4 ^ (r & 7))) * 16);
    }

    // accumulators: 5 cues x 2 packed f32x2
    unsigned long long acc[NCUE][2];
#pragma unroll
    for (int c = 0; c < NCUE; c++) { acc[c][0] = 0ull; acc[c][1] = 0ull; }

    const unsigned rbase0 = sb0 + (unsigned)(t * F4ROW * 16);
    const unsigned cbase  = (unsigned)__cvta_generic_to_shared(cue_sm);

#define ISSUE_STAGE(bufsel)                                                    \
    do {                                                                       \
        unsigned _boff = (bufsel) ? (unsigned)(STAGE_F4 * 16) : 0u;            \
        _Pragma("unroll")                                                      \
        for (int _p = 0; _p < 8; _p++) {                                       \
            cp16(sdst[_p] + _boff, gsrc[_p]);                                  \
            gsrc[_p] += F4ROW;  /* advance 32 floats to next stage */          \
        }                                                                      \
        asm volatile("cp.async.commit_group;" ::: "memory");                   \
    } while (0)

    ISSUE_STAGE(0);     // stage 0 -> buf 0
    ISSUE_STAGE(1);     // stage 1 -> buf 1

    for (int s = 0; s < NS; s++) {
        if (s < NS - 1) asm volatile("cp.async.wait_group 1;" ::: "memory");
        else            asm volatile("cp.async.wait_group 0;" ::: "memory");
        __syncthreads();

        const unsigned rb = rbase0 + ((s & 1) ? (unsigned)(STAGE_F4 * 16) : 0u);
        const unsigned cb = cbase + (unsigned)(s * DC * 4);
#pragma unroll
        for (int j4 = 0; j4 < F4ROW; j4++) {
            unsigned long long plo, phi;
            lds_v2u64(plo, phi, rb + (unsigned)((j4 ^ (t & 7)) * 16));
#pragma unroll
            for (int c = 0; c < NCUE; c++) {
                unsigned long long qlo, qhi;
                lds_v2u64(qlo, qhi, cb + (unsigned)(c * D * 4 + j4 * 16));
                fma2(acc[c][0], plo, qlo);
                fma2(acc[c][1], phi, qhi);
            }
        }
        __syncthreads();                 // buf (s&1) free to overwrite
        if (s + 2 < NS) ISSUE_STAGE(s & 1);
    }
#undef ISSUE_STAGE

    // finalize: per-thread sims -> packed keys -> warp/block/global max
    const int pidx = min(p0 + t, NPATCH - 1);
    const unsigned lowbits = 0xFFFFFFFFu - (unsigned)pidx;
    unsigned long long key[NCUE];
#pragma unroll
    for (int c = 0; c < NCUE; c++) {
        float a0 = __uint_as_float((unsigned)(acc[c][0] & 0xFFFFFFFFull));
        float a1 = __uint_as_float((unsigned)(acc[c][0] >> 32));
        float a2 = __uint_as_float((unsigned)(acc[c][1] & 0xFFFFFFFFull));
        float a3 = __uint_as_float((unsigned)(acc[c][1] >> 32));
        float sim = (a0 + a1) + (a2 + a3);
        key[c] = ((unsigned long long)f2key(sim) << 32) | lowbits;
    }
#pragma unroll
    for (int c = 0; c < NCUE; c++)
#pragma unroll
        for (int o = 16; o; o >>= 1) {
            unsigned long long other = __shfl_xor_sync(0xffffffffu, key[c], o);
            key[c] = (other > key[c]) ? other : key[c];
        }
    const int warp = t >> 5, lane = t & 31;
    if (lane == 0)
#pragma unroll
        for (int c = 0; c < NCUE; c++) warp_best[warp][c] = key[c];
    __syncthreads();
    if (t < NCUE) {
        unsigned long long m = warp_best[0][t];
#pragma unroll
        for (int w = 1; w < TPB / 32; w++)
            m = (warp_best[w][t] > m) ? warp_best[w][t] : m;
        atomicMax(&g_best[b * NCUE + t], m);
    }
}

// ---------------------------------------------------------------------------
// Kernel 2: build + normalize 10 output tokens per batch, then reset g_best
// so every graph replay starts from zeroed scratch (deterministic).
// ---------------------------------------------------------------------------
__global__ __launch_bounds__(256) void gather_kernel(const float* __restrict__ tokens,
                                                     float* __restrict__ out) {
    const int tk = blockIdx.x;
    const int b  = blockIdx.y;
    const float* base = tokens + (size_t)b * STOK * D;
    const int tid = threadIdx.x;

    float v[3];

    if (tk < NCUE) {
        const float* row = base + (size_t)tk * D;
#pragma unroll
        for (int j = 0; j < 3; j++) v[j] = row[tid + 256 * j];
    } else {
        const int c = tk - NCUE;
        const unsigned long long key = g_best[b * NCUE + c];
        const int idx = (int)(0xFFFFFFFFu - (unsigned)(key & 0xFFFFFFFFull));
        const int h = idx / G, w = idx % G;
        const int r0 = max(h - 1, 0), r1 = min(h + 1, G - 1);
        const int c0 = max(w - 1, 0), c1 = min(w + 1, G - 1);
        const float inv = 1.0f / (float)((r1 - r0 + 1) * (c1 - c0 + 1));
#pragma unroll
        for (int j = 0; j < 3; j++) v[j] = 0.0f;
        for (int r = r0; r <= r1; r++)
            for (int cc = c0; cc <= c1; cc++) {
                const float* prow = base + (size_t)(NCUE + r * G + cc) * D;
#pragma unroll
                for (int j = 0; j < 3; j++) v[j] += prow[tid + 256 * j];
            }
#pragma unroll
        for (int j = 0; j < 3; j++) v[j] *= inv;
    }

    // block reduce sum of squares
    float ss = v[0] * v[0] + v[1] * v[1] + v[2] * v[2];
#pragma unroll
    for (int o = 16; o > 0; o >>= 1) ss += __shfl_xor_sync(0xffffffffu, ss, o);

    __shared__ float red[8];
    const int lane = tid & 31, warp = tid >> 5;
    if (lane == 0) red[warp] = ss;
    __syncthreads();   // also orders all g_best reads before the reset below
    if (warp == 0) {
        float s2 = (lane < 8) ? red[lane] : 0.0f;
        s2 += __shfl_xor_sync(0xffffffffu, s2, 4);
        s2 += __shfl_xor_sync(0xffffffffu, s2, 2);
        s2 += __shfl_xor_sync(0xffffffffu, s2, 1);
        if (lane == 0) red[0] = s2;
    }
    // reset scratch for the next replay (exactly one block owns each slot)
    if (tk >= NCUE && tid == 0) g_best[b * NCUE + (tk - NCUE)] = 0ull;
    __syncthreads();

    const float norm  = sqrtf(red[0]);
    const float scale = 1.0f / fmaxf(norm, EPSN);

    float* orow = out + ((size_t)b * 10 + tk) * D;
#pragma unroll
    for (int j = 0; j < 3; j++) orow[tid + 256 * j] = v[j] * scale;
}

extern "C" void kernel_launch(void* const* d_in, const int* in_sizes, int n_in,
                              void* d_out, int out_size) {
    const float* tokens = (const float*)d_in[0];
    float* out = (float*)d_out;

    argmax_kernel<<<dim3(NTILE, BATCH), TPB>>>(tokens);
    gather_kernel<<<dim3(10, BATCH), 256>>>(tokens, out);
}